// round 4
// baseline (speedup 1.0000x reference)
#include <cuda_runtime.h>

#define BATCH 4
#define C1    32
#define C2    64
#define MROWS 512
#define NB    128
#define NT    512

// Intermediates (no allocation allowed -> __device__ globals)
__device__ float g_z1 [BATCH * C1 * 256];        // conv1 out: [b][ic][16x16]
__device__ float g_z2t[BATCH * 64 * C2];         // conv2 out, token-major: [b][pix][oc]
__device__ __align__(16) float g_V[MROWS * C2];  // lookup @ Wv
__device__ unsigned g_bar;                       // monotonic grid-barrier ticket

// Software grid barrier: valid because all NB blocks are co-resident
// (128 blocks <= 148 SMs, 512 thr, <48KB smem). Monotonic counter -> safe
// across graph replays with no reset.
__device__ __forceinline__ void gridbar() {
    __threadfence();
    __syncthreads();
    if (threadIdx.x == 0) {
        unsigned ticket = atomicAdd(&g_bar, 1u);
        unsigned target = (ticket / NB + 1u) * NB;
        while (*(volatile unsigned*)&g_bar < target) { }
        __threadfence();
    }
    __syncthreads();
}

__global__ void __launch_bounds__(NT) fused_kernel(
    const float* __restrict__ x,  const float* __restrict__ w1, const float* __restrict__ b1,
    const float* __restrict__ w2, const float* __restrict__ b2,
    const float* __restrict__ lookup, const float* __restrict__ Wv,
    const float* __restrict__ Wo, float* __restrict__ out)
{
    __shared__ __align__(16) float sm[8704];   // 34 KB, reused per phase
    int t    = threadIdx.x;
    int blk  = blockIdx.x;
    int lane = t & 31, warp = t >> 5;

    // ============ Phase A: conv1 (t<256) || vmat V=lookup@Wv (t>=256) =======
    // stage: conv1 weights for (blk&31) oc  +  this block's 4 lookup rows
    if (t < 48)   sm[t] = w1[(blk & 31) * 48 + t];
    if (t >= 256) sm[64 + (t - 256)] = lookup[blk * 256 + (t - 256)];
    __syncthreads();

    if (t < 256) {
        // conv1: block -> (b, oc); thread -> output pixel. k4 s2 p1 relu.
        int b = blk >> 5, oc = blk & 31;
        int oh = t >> 4, ow = t & 15;
        int iw0 = ow * 2 - 1;
        float acc = b1[oc];
        #pragma unroll
        for (int ic = 0; ic < 3; ic++) {
            const float* xp  = x + (b * 3 + ic) * 1024;
            const float* swp = sm + ic * 16;
            #pragma unroll
            for (int kh = 0; kh < 4; kh++) {
                int ih = oh * 2 - 1 + kh;
                if ((unsigned)ih < 32u) {
                    const float* xr = xp + ih * 32;
                    if (iw0 >= 0)  acc += xr[iw0]     * swp[kh * 4];
                    acc += xr[iw0 + 1] * swp[kh * 4 + 1];
                    acc += xr[iw0 + 2] * swp[kh * 4 + 2];
                    if (iw0 < 29)  acc += xr[iw0 + 3] * swp[kh * 4 + 3];
                }
            }
        }
        g_z1[(b * C1 + oc) * 256 + t] = fmaxf(acc, 0.0f);
    } else {
        // vmat: 256 outputs per block, rows staged in smem, Wv coalesced.
        int i = t - 256;
        int d = i & 63;
        const float* row = sm + 64 + (i >> 6) * 64;
        float a0 = 0.f, a1 = 0.f, a2 = 0.f, a3 = 0.f;
        #pragma unroll
        for (int k = 0; k < 64; k += 4) {
            a0 += row[k]     * Wv[(k    ) * 64 + d];
            a1 += row[k + 1] * Wv[(k + 1) * 64 + d];
            a2 += row[k + 2] * Wv[(k + 2) * 64 + d];
            a3 += row[k + 3] * Wv[(k + 3) * 64 + d];
        }
        g_V[blk * 256 + i] = (a0 + a1) + (a2 + a3);
    }
    gridbar();

    // ============ Phase B: conv2 -> g_z2t (token-major) =====================
    // block -> (b, oc-pair); 4 threads per output (ic split by 8); z1[b] in smem.
    {
        int b = blk >> 5, ocp = blk & 31;
        float4* sz4 = (float4*)sm;
        const float4* z14 = (const float4*)(g_z1 + b * 8192);
        #pragma unroll
        for (int i = t; i < 2048; i += NT) sz4[i] = z14[i];
        __syncthreads();

        int seg = t & 3, pix = (t >> 2) & 63, ocl = t >> 8;
        int oc = ocp * 2 + ocl;
        int oh = pix >> 3, ow = pix & 7;
        int iw0 = ow * 2 - 1;
        const float4* W4 = (const float4*)(w2 + (oc * C1 + seg * 8) * 16);
        float acc = 0.f;
        #pragma unroll
        for (int ic = 0; ic < 8; ic++) {
            const float* zp = sm + (seg * 8 + ic) * 256;
            #pragma unroll
            for (int kh = 0; kh < 4; kh++) {
                int ih = oh * 2 - 1 + kh;
                if ((unsigned)ih < 16u) {
                    float4 w = W4[ic * 4 + kh];
                    const float* zr = zp + ih * 16;
                    if (iw0 >= 0)  acc += zr[iw0]     * w.x;
                    acc += zr[iw0 + 1] * w.y;
                    acc += zr[iw0 + 2] * w.z;
                    if (iw0 < 13)  acc += zr[iw0 + 3] * w.w;
                }
            }
        }
        sm[8192 + t] = acc;            // partial for (ocl, pix, seg)
        __syncthreads();
        if (t < 128) {
            int o2 = t >> 6, px = t & 63;
            int base = 8192 + o2 * 256 + px * 4;
            float v = (sm[base] + sm[base + 1]) + (sm[base + 2] + sm[base + 3])
                      + b2[ocp * 2 + o2];
            g_z2t[(b * 64 + px) * 64 + ocp * 2 + o2] = fmaxf(v, 0.0f);
        }
    }
    gridbar();

    // ============ Phase C: Hopfield retrieve, 2 tokens per block ============
    {
        float* st   = sm;          // 128: the 2 token vectors
        float* ss0  = sm + 128;    // 512
        float* ss1  = sm + 640;    // 512
        float* red  = sm + 1152;   // 64
        float* part = sm + 1216;   // 4096
        float* pre  = sm + 5312;   // 128
        float* pf   = sm + 5440;   // 512

        int b = blk >> 5, p0 = (blk & 31) * 2;
        if (t < 128) st[t] = g_z2t[(b * 64 + p0) * 64 + t];   // both tokens contiguous
        __syncthreads();

        // ---- scores: half-warp per row, lanes split k (float4), coalesced ----
        int half = lane >> 4, kq = lane & 15;
        float4 tu = *(const float4*)(st + kq * 4);        // token0 chunk (regs)
        float4 tv = *(const float4*)(st + 64 + kq * 4);   // token1 chunk (regs)
        int m0r = warp * 32;
        #pragma unroll
        for (int r = 0; r < 32; r += 2) {
            int m = m0r + r + half;
            float4 L = *(const float4*)(lookup + m * 64 + kq * 4);
            float p0s = L.x * tu.x + L.y * tu.y + L.z * tu.z + L.w * tu.w;
            float p1s = L.x * tv.x + L.y * tv.y + L.z * tv.z + L.w * tv.w;
            #pragma unroll
            for (int o = 8; o; o >>= 1) {
                p0s += __shfl_xor_sync(0xffffffffu, p0s, o);
                p1s += __shfl_xor_sync(0xffffffffu, p1s, o);
            }
            if (kq == 0) { ss0[m] = p0s * 0.125f; ss1[m] = p1s * 0.125f; }
        }
        __syncthreads();

        // ---- dual softmax over 512 (thread t <-> row t) ----
        float a = ss0[t], c = ss1[t];
        float mx0 = a, mx1 = c;
        #pragma unroll
        for (int o = 16; o; o >>= 1) {
            mx0 = fmaxf(mx0, __shfl_xor_sync(0xffffffffu, mx0, o));
            mx1 = fmaxf(mx1, __shfl_xor_sync(0xffffffffu, mx1, o));
        }
        if (lane == 0) { red[warp] = mx0; red[16 + warp] = mx1; }
        __syncthreads();
        mx0 = red[0]; mx1 = red[16];
        #pragma unroll
        for (int i = 1; i < 16; i++) {
            mx0 = fmaxf(mx0, red[i]); mx1 = fmaxf(mx1, red[16 + i]);
        }
        float e0 = __expf(a - mx0), e1 = __expf(c - mx1);
        ss0[t] = e0; ss1[t] = e1;
        float s0 = e0, s1 = e1;
        #pragma unroll
        for (int o = 16; o; o >>= 1) {
            s0 += __shfl_xor_sync(0xffffffffu, s0, o);
            s1 += __shfl_xor_sync(0xffffffffu, s1, o);
        }
        if (lane == 0) { red[32 + warp] = s0; red[48 + warp] = s1; }
        __syncthreads();
        float tot0 = red[32], tot1 = red[48];
        #pragma unroll
        for (int i = 1; i < 16; i++) { tot0 += red[32 + i]; tot1 += red[48 + i]; }
        float inv0 = __frcp_rn(tot0), inv1 = __frcp_rn(tot1);

        // ---- p@V: thread=(g:32 m-groups, q:16 d-quads); V coalesced ----
        int g = t >> 4, q = t & 15;
        const float4* V4 = (const float4*)g_V;
        float4 A  = make_float4(0.f, 0.f, 0.f, 0.f);
        float4 Bv = make_float4(0.f, 0.f, 0.f, 0.f);
        int mb = g * 16;
        #pragma unroll
        for (int m = mb; m < mb + 16; m++) {
            float4 v = V4[m * 16 + q];
            float pa = ss0[m], pb = ss1[m];
            A.x  += pa * v.x; A.y  += pa * v.y; A.z  += pa * v.z; A.w  += pa * v.w;
            Bv.x += pb * v.x; Bv.y += pb * v.y; Bv.z += pb * v.z; Bv.w += pb * v.w;
        }
        *(float4*)(part + g * 64 + q * 4)        = A;
        *(float4*)(part + 2048 + g * 64 + q * 4) = Bv;
        __syncthreads();
        if (t < 128) {
            int j = t >> 6, d = t & 63;
            const float* pp = part + j * 2048;
            float s = 0.f;
            #pragma unroll
            for (int gg = 0; gg < 32; gg++) s += pp[gg * 64 + d];
            pre[j * 64 + d] = s * (j ? inv1 : inv0);
        }
        __syncthreads();

        // ---- @Wo: thread=(h4:0..3 d-range, j: token, e); Wo coalesced ----
        {
            int e = t & 63, j = (t >> 6) & 1, h4 = t >> 7;
            const float* pj = pre + j * 64;
            float acc = 0.f;
            int d0 = h4 * 16;
            #pragma unroll
            for (int d = d0; d < d0 + 16; d++) acc += pj[d] * Wo[d * 64 + e];
            pf[t] = acc;
        }
        __syncthreads();
        if (t < 128) {
            int j = t >> 6, e = t & 63;
            out[b * 4096 + e * 64 + p0 + j] =
                (pf[t] + pf[t + 128]) + (pf[t + 256] + pf[t + 384]);
        }
    }
}

// ---------------------------------------------------------------------------
extern "C" void kernel_launch(void* const* d_in, const int* in_sizes, int n_in,
                              void* d_out, int out_size) {
    const float* x       = (const float*)d_in[0];
    const float* conv1_w = (const float*)d_in[1];
    const float* conv1_b = (const float*)d_in[2];
    const float* conv2_w = (const float*)d_in[3];
    const float* conv2_b = (const float*)d_in[4];
    const float* lookup  = (const float*)d_in[5];
    const float* Wv      = (const float*)d_in[6];
    const float* Wo      = (const float*)d_in[7];
    float* out = (float*)d_out;

    fused_kernel<<<NB, NT>>>(x, conv1_w, conv1_b, conv2_w, conv2_b,
                             lookup, Wv, Wo, out);
}